// round 15
// baseline (speedup 1.0000x reference)
#include <cuda_runtime.h>
#include <math.h>

#define B_ 32
#define T_ 720
#define N_ 321

constexpr int L0C = 7395840;          // 32*720*321
constexpr int L1C = 3697927;          // (L0+15)//2
constexpr int L2C = 1848971;
constexpr int L3C = 924493;
constexpr int R2C = 2 * L3C - 14;     // 1848972
constexpr int R1C = 2 * L2C - 14;     // 3697928
constexpr long long KMED = (L1C - 1) / 2;

// padded (16B-aligned) buffer lengths
constexpr int L1P = 3697928;
constexpr int L2P = 1848972;
constexpr int L3P = 924496;

constexpr long long CHAIN = 2LL * L1P + 2LL * L2P + 2LL * L3P + R2C + R1C;
constexpr size_t SCRATCH_SZ = (size_t)2 * L0C + 2 * CHAIN;

constexpr int H20 = 1 << 20;          // 20-bit histogram bins per chain

// sym8 filters -> FFMA immediates after unroll
__device__ constexpr float LO[16] = {
    -3.3824159510061256e-03f, -5.4213233179114810e-04f,  3.1695087811492980e-02f,
     7.6074873249176050e-03f, -1.4329423835080970e-01f, -6.1273359067658524e-02f,
     4.8135965125837220e-01f,  7.7718575170052350e-01f,  3.6444189483533895e-01f,
    -5.1945838107709040e-02f, -2.7219029917056003e-02f,  4.9137179673607506e-02f,
     3.8087520138906150e-03f, -1.4952258337048230e-02f, -3.0292051472136680e-04f,
     1.8899503327594609e-03f
};
__device__ constexpr float HI[16] = {
    -1.8899503327594609e-03f, -3.0292051472136680e-04f,  1.4952258337048230e-02f,
     3.8087520138906150e-03f, -4.9137179673607506e-02f, -2.7219029917056003e-02f,
     5.1945838107709040e-02f,  3.6444189483533895e-01f, -7.7718575170052350e-01f,
     4.8135965125837220e-01f,  6.1273359067658524e-02f, -1.4329423835080970e-01f,
    -7.6074873249176050e-03f,  3.1695087811492980e-02f,  5.4213233179114810e-04f,
    -3.3824159510061256e-03f
};

struct SelState {
    unsigned int prefix;
    unsigned long long k;
    float lam;
};

__device__ __align__(16) float g_scratch[SCRATCH_SZ];
__device__ unsigned int g_hist[2 * 4096];     // pass-0 bins; re-zeroed by select0
__device__ unsigned int g_hist20[2 * H20];    // pass-1 bins; re-zeroed by memset each replay
__device__ unsigned int g_chunk[2 * 1024];    // chunk sums; re-zeroed by selectF
__device__ SelState g_sel[2];

// ---------------------------------------------------------------------------
// moving average (K=25, edge-replicated): rolling register ring (R14 WIN)
// ---------------------------------------------------------------------------
#define MA_CH 48
#define MA_NCH (T_ / MA_CH)

__device__ __forceinline__ int clampT(int t) { return min(max(t, 0), T_ - 1); }

__global__ __launch_bounds__(256)
void movavg_kernel(const float* __restrict__ x,
                   float* __restrict__ trend, float* __restrict__ res) {
    int tid = blockIdx.x * blockDim.x + threadIdx.x;
    int total = B_ * MA_NCH * N_;
    if (tid >= total) return;
    int n = tid % N_;
    int r = tid / N_;
    int ch = r % MA_NCH;
    int b = r / MA_NCH;

    const float* xb = x + (size_t)b * T_ * N_ + n;
    float* tb = trend + (size_t)b * T_ * N_ + n;
    float* rb = res + (size_t)b * T_ * N_ + n;

    int t0 = ch * MA_CH;

    float w[26];
    #pragma unroll
    for (int k = 0; k < 25; ++k)
        w[k] = __ldg(xb + (size_t)clampT(t0 - 12 + k) * N_);
    float s = 0.f;
    #pragma unroll
    for (int k = 0; k < 25; ++k) s += w[k];

    #pragma unroll
    for (int st = 0; st < MA_CH; ++st) {
        int t = t0 + st;
        w[(25 + st) % 26] = __ldg(xb + (size_t)clampT(t + 13) * N_);
        float xc = w[(12 + st) % 26];
        float tr = s / 25.0f;
        tb[(size_t)t * N_] = tr;
        rb[(size_t)t * N_] = xc - tr;
        s += w[(25 + st) % 26] - w[st % 26];
    }
}

// ---------------------------------------------------------------------------
// forward DWT, 4 output-pairs per thread (R3)
// ---------------------------------------------------------------------------
__device__ __forceinline__ void dwt_compute4(const float* __restrict__ a, int L,
                                             int tid, float accA[4], float accD[4]) {
    float w[24];
    int s0 = 8 * tid - 16;
    if (s0 >= 0 && s0 + 24 <= L) {
        const float4* p = reinterpret_cast<const float4*>(a + s0);
        #pragma unroll
        for (int q = 0; q < 6; ++q) {
            float4 v = __ldg(p + q);
            w[4*q+0] = v.x; w[4*q+1] = v.y; w[4*q+2] = v.z; w[4*q+3] = v.w;
        }
    } else {
        #pragma unroll
        for (int q = 0; q < 24; ++q) {
            int s = s0 + q;
            if (s < 0) s = -1 - s;
            else if (s >= L) s = 2 * L - 1 - s;
            w[q] = __ldg(a + s);
        }
    }
    #pragma unroll
    for (int c = 0; c < 4; ++c) {
        float sa = 0.f, sd = 0.f;
        #pragma unroll
        for (int t = 0; t < 16; ++t) {
            float v = w[2*c + 17 - t];
            sa = fmaf(v, LO[t], sa);
            sd = fmaf(v, HI[t], sd);
        }
        accA[c] = sa; accD[c] = sd;
    }
}

__global__ __launch_bounds__(256)
void dwt4_kernel(const float* __restrict__ abase, long long astr, int L,
                 float* __restrict__ cabase, float* __restrict__ cdbase,
                 long long cstr, int Lc) {
    int chain = blockIdx.y;
    const float* a = abase + (size_t)chain * astr;
    float* ca = cabase + (size_t)chain * cstr;
    float* cd = cdbase + (size_t)chain * cstr;
    int tid = blockIdx.x * blockDim.x + threadIdx.x;
    int j0 = 4 * tid;
    if (j0 >= Lc) return;
    float accA[4], accD[4];
    dwt_compute4(a, L, tid, accA, accD);
    if (j0 + 4 <= Lc) {
        *reinterpret_cast<float4*>(ca + j0) = make_float4(accA[0], accA[1], accA[2], accA[3]);
        *reinterpret_cast<float4*>(cd + j0) = make_float4(accD[0], accD[1], accD[2], accD[3]);
    } else {
        for (int c = 0; c < 4 && j0 + c < Lc; ++c) { ca[j0+c] = accA[c]; cd[j0+c] = accD[c]; }
    }
}

// level-1 dwt with fused median pass-0 histogram (top 11 bits of |cd|)
__global__ __launch_bounds__(256)
void dwt4_hist_kernel(const float* __restrict__ abase, long long astr, int L,
                      float* __restrict__ cabase, float* __restrict__ cdbase,
                      long long cstr, int Lc, unsigned int* __restrict__ histb) {
    __shared__ unsigned int sh[4096];
    for (int i = threadIdx.x; i < 4096; i += 256) sh[i] = 0u;
    __syncthreads();

    int chain = blockIdx.y;
    int tid = blockIdx.x * blockDim.x + threadIdx.x;
    int j0 = 4 * tid;
    if (j0 < Lc) {
        const float* a = abase + (size_t)chain * astr;
        float* ca = cabase + (size_t)chain * cstr;
        float* cd = cdbase + (size_t)chain * cstr;
        float accA[4], accD[4];
        dwt_compute4(a, L, tid, accA, accD);
        if (j0 + 4 <= Lc) {
            *reinterpret_cast<float4*>(ca + j0) = make_float4(accA[0], accA[1], accA[2], accA[3]);
            *reinterpret_cast<float4*>(cd + j0) = make_float4(accD[0], accD[1], accD[2], accD[3]);
            #pragma unroll
            for (int c = 0; c < 4; ++c)
                atomicAdd(&sh[__float_as_uint(fabsf(accD[c])) >> 20], 1u);
        } else {
            for (int c = 0; c < 4 && j0 + c < Lc; ++c) {
                ca[j0+c] = accA[c]; cd[j0+c] = accD[c];
                atomicAdd(&sh[__float_as_uint(fabsf(accD[c])) >> 20], 1u);
            }
        }
    }
    __syncthreads();
    unsigned int* h = histb + chain * 4096;
    for (int i = threadIdx.x; i < 4096; i += 256) {
        unsigned int c = sh[i];
        if (c) atomicAdd(&h[i], c);
    }
}

// pass-0 radix select over 4096 bins (re-zeros bins for replay)
__global__ __launch_bounds__(256)
void select0_kernel(unsigned int* __restrict__ histb, SelState* __restrict__ selb) {
    int chain = blockIdx.x;
    unsigned int* hist = histb + chain * 4096;
    SelState* st = selb + chain;
    __shared__ unsigned int sbins[4096];
    __shared__ unsigned long long ps[256];
    int tid = threadIdx.x;
    unsigned long long s = 0;
    #pragma unroll
    for (int j = 0; j < 16; ++j) {
        unsigned int c = hist[tid * 16 + j];
        sbins[tid * 16 + j] = c;
        s += c;
        hist[tid * 16 + j] = 0u;
    }
    ps[tid] = s;
    __syncthreads();
    if (tid == 0) {
        long long k = (long long)KMED;
        long long cum = 0;
        int chunk = 0;
        for (; chunk < 255; ++chunk) {
            if (cum + (long long)ps[chunk] > k) break;
            cum += (long long)ps[chunk];
        }
        int b = chunk * 16;
        for (;; ++b) {
            unsigned int c = sbins[b];
            if (cum + (long long)c > k) break;
            cum += c;
        }
        st->k = (unsigned long long)(k - cum);
        st->prefix = (unsigned int)b;
    }
}

// ---------------------------------------------------------------------------
// pass 1: scan d1, bin the remaining 20 bits of matching elements (global hist)
// ---------------------------------------------------------------------------
__global__ __launch_bounds__(256)
void histP20_kernel(const float* __restrict__ dbase, long long str, int len,
                    unsigned int* __restrict__ h20b,
                    const SelState* __restrict__ sel) {
    int chain = blockIdx.y;
    const float* d = dbase + (size_t)chain * str;
    unsigned int* h = h20b + (size_t)chain * H20;
    unsigned int pfx = sel[chain].prefix;

    int nvec = len >> 2;
    int stride = gridDim.x * blockDim.x;
    const float4* dv = reinterpret_cast<const float4*>(d);
    for (int i = blockIdx.x * blockDim.x + threadIdx.x; i < nvec; i += stride) {
        float4 v = __ldg(dv + i);
        float vv[4] = {v.x, v.y, v.z, v.w};
        #pragma unroll
        for (int q = 0; q < 4; ++q) {
            unsigned int u = __float_as_uint(fabsf(vv[q]));
            if ((u >> 20) == pfx) atomicAdd(&h[u & 0xFFFFFu], 1u);
        }
    }
    if (blockIdx.x == 0 && threadIdx.x < (len & 3)) {
        unsigned int u = __float_as_uint(fabsf(__ldg(d + (nvec << 2) + threadIdx.x)));
        if ((u >> 20) == pfx) atomicAdd(&h[u & 0xFFFFFu], 1u);
    }
}

// chunk sums: block (bx, chain) sums bins [bx*1024, +1024)
__global__ __launch_bounds__(256)
void reduce20_kernel(const unsigned int* __restrict__ h20b,
                     unsigned int* __restrict__ chunkb) {
    int chain = blockIdx.y;
    const uint4* p = reinterpret_cast<const uint4*>(
        h20b + (size_t)chain * H20 + (size_t)blockIdx.x * 1024);
    __shared__ unsigned int sps[256];
    uint4 v = __ldg(p + threadIdx.x);
    sps[threadIdx.x] = v.x + v.y + v.z + v.w;
    __syncthreads();
    for (int off = 128; off > 0; off >>= 1) {
        if (threadIdx.x < off) sps[threadIdx.x] += sps[threadIdx.x + off];
        __syncthreads();
    }
    if (threadIdx.x == 0) chunkb[chain * 1024 + blockIdx.x] = sps[0];
}

// final select: find chunk, then bin; lam = f(median). Re-zeros chunk sums.
__global__ __launch_bounds__(256)
void selectF_kernel(const unsigned int* __restrict__ h20b,
                    unsigned int* __restrict__ chunkb,
                    SelState* __restrict__ selb) {
    int chain = blockIdx.x;
    const unsigned int* h = h20b + (size_t)chain * H20;
    unsigned int* chunk = chunkb + chain * 1024;
    SelState* st = selb + chain;
    __shared__ unsigned int sc[1024];
    __shared__ unsigned long long ps[256];
    __shared__ int tcS;
    __shared__ long long kbS;
    int tid = threadIdx.x;

    unsigned long long s = 0;
    #pragma unroll
    for (int j = 0; j < 4; ++j) {
        unsigned int c = chunk[tid * 4 + j];
        sc[tid * 4 + j] = c;
        s += c;
        chunk[tid * 4 + j] = 0u;   // re-zero for replay
    }
    ps[tid] = s;
    __syncthreads();
    if (tid == 0) {
        long long k = (long long)st->k;
        long long cum = 0;
        int t = 0;
        for (; t < 255; ++t) {
            if (cum + (long long)ps[t] > k) break;
            cum += (long long)ps[t];
        }
        int c4 = t * 4;
        for (;; ++c4) {
            unsigned int c = sc[c4];
            if (cum + (long long)c > k) break;
            cum += c;
        }
        tcS = c4;
        kbS = k - cum;
    }
    __syncthreads();
    int tc = tcS;
    const uint4* p = reinterpret_cast<const uint4*>(h + (size_t)tc * 1024);
    uint4 v = __ldg(p + tid);
    sc[4*tid+0] = v.x; sc[4*tid+1] = v.y; sc[4*tid+2] = v.z; sc[4*tid+3] = v.w;
    __syncthreads();
    if (tid == 0) {
        long long k = kbS;
        long long cum = 0;
        int b = 0;
        for (;; ++b) {
            unsigned int c = sc[b];
            if (cum + (long long)c > k) break;
            cum += c;
        }
        unsigned int u = (st->prefix << 20) | ((unsigned int)tc * 1024u + (unsigned int)b);
        float med = __uint_as_float(u);
        st->lam = (med / 0.6745f) * (float)sqrt(2.0 * log((double)L0C));
    }
}

// ---------------------------------------------------------------------------
// inverse DWT with fused thresholding, 8 outputs/thread (R3)
// ---------------------------------------------------------------------------
__device__ __forceinline__ float thrf(float d, float lam, float alam) {
    float ad = fabsf(d);
    return (ad >= lam) ? copysignf(ad - alam, d) : 0.0f;
}

__device__ __forceinline__ void idwt_compute8(const float* __restrict__ ca,
                                              const float* __restrict__ cd,
                                              int Lc, int t, float lam, float alam,
                                              float o[8]) {
    int i0 = 4 * t;
    float A[12], D[12];
    if (i0 + 12 <= Lc) {
        const float4* pa = reinterpret_cast<const float4*>(ca + i0);
        const float4* pd = reinterpret_cast<const float4*>(cd + i0);
        #pragma unroll
        for (int q = 0; q < 3; ++q) {
            float4 va = __ldg(pa + q);
            A[4*q+0] = va.x; A[4*q+1] = va.y; A[4*q+2] = va.z; A[4*q+3] = va.w;
            float4 vd = __ldg(pd + q);
            D[4*q+0] = thrf(vd.x, lam, alam); D[4*q+1] = thrf(vd.y, lam, alam);
            D[4*q+2] = thrf(vd.z, lam, alam); D[4*q+3] = thrf(vd.w, lam, alam);
        }
    } else {
        #pragma unroll
        for (int q = 0; q < 12; ++q) {
            int i = i0 + q;
            bool ok = i < Lc;
            A[q] = ok ? __ldg(ca + i) : 0.f;
            D[q] = ok ? thrf(__ldg(cd + i), lam, alam) : 0.f;
        }
    }
    #pragma unroll
    for (int c = 0; c < 8; ++c) {
        int base = c >> 1;
        int tb = (c & 1) ? 0 : 1;
        float v = 0.f;
        #pragma unroll
        for (int r = 0; r < 8; ++r) {
            v = fmaf(A[base + r], LO[2*r + tb], v);
            v = fmaf(D[base + r], HI[2*r + tb], v);
        }
        o[c] = v;
    }
}

__global__ __launch_bounds__(256)
void idwt8_kernel(const float* __restrict__ cabase, const float* __restrict__ cdbase,
                  long long str, int Lc, float* __restrict__ outbase, long long ostr,
                  const SelState* __restrict__ sel) {
    int chain = blockIdx.y;
    const float* ca = cabase + (size_t)chain * str;
    const float* cd = cdbase + (size_t)chain * str;
    float* out = outbase + (size_t)chain * ostr;
    int t = blockIdx.x * blockDim.x + threadIdx.x;
    int Lout = 2 * Lc - 14;
    int k0 = 8 * t;
    if (k0 >= Lout) return;
    float lam = sel[chain].lam, alam = 0.85f * lam;
    float o[8];
    idwt_compute8(ca, cd, Lc, t, lam, alam, o);
    if (k0 + 8 <= Lout) {
        *reinterpret_cast<float4*>(out + k0)     = make_float4(o[0], o[1], o[2], o[3]);
        *reinterpret_cast<float4*>(out + k0 + 4) = make_float4(o[4], o[5], o[6], o[7]);
    } else {
        for (int c = 0; c < 8 && k0 + c < Lout; ++c) out[k0 + c] = o[c];
    }
}

// final level: fuse the four output writes
__global__ __launch_bounds__(256)
void fidwt8_kernel(const float* __restrict__ cabase, const float* __restrict__ cdbase,
                   long long str, int Lc, const float* __restrict__ sigbase,
                   long long sstr, float* __restrict__ out,
                   const SelState* __restrict__ sel) {
    int chain = blockIdx.y;
    const float* ca = cabase + (size_t)chain * str;
    const float* cd = cdbase + (size_t)chain * str;
    const float* sig = sigbase + (size_t)chain * sstr;
    float* out_diff = out + (size_t)(2 * chain) * L0C;
    float* out_nn   = out + (size_t)(2 * chain + 1) * L0C;
    int t = blockIdx.x * blockDim.x + threadIdx.x;
    int Lout = 2 * Lc - 14;   // == L0C (mult of 8)
    int k0 = 8 * t;
    if (k0 >= Lout) return;
    float lam = sel[chain].lam, alam = 0.85f * lam;
    float o[8];
    idwt_compute8(ca, cd, Lc, t, lam, alam, o);
    float4 s0 = __ldg(reinterpret_cast<const float4*>(sig + k0));
    float4 s1 = __ldg(reinterpret_cast<const float4*>(sig + k0 + 4));
    *reinterpret_cast<float4*>(out_nn + k0)     = make_float4(o[0], o[1], o[2], o[3]);
    *reinterpret_cast<float4*>(out_nn + k0 + 4) = make_float4(o[4], o[5], o[6], o[7]);
    *reinterpret_cast<float4*>(out_diff + k0) =
        make_float4(s0.x - o[0], s0.y - o[1], s0.z - o[2], s0.w - o[3]);
    *reinterpret_cast<float4*>(out_diff + k0 + 4) =
        make_float4(s1.x - o[4], s1.y - o[5], s1.z - o[6], s1.w - o[7]);
}

// ---------------------------------------------------------------------------
static inline int gridFor(long long n, int per) { return (int)((n + per - 1) / per); }

extern "C" void kernel_launch(void* const* d_in, const int* in_sizes, int n_in,
                              void* d_out, int out_size) {
    const float* x = (const float*)d_in[0];
    float* out = (float*)d_out;

    float* scr = nullptr;
    unsigned int* hist = nullptr;
    unsigned int* h20 = nullptr;
    unsigned int* chk = nullptr;
    SelState* sel = nullptr;
    cudaGetSymbolAddress((void**)&scr, g_scratch);
    cudaGetSymbolAddress((void**)&hist, g_hist);
    cudaGetSymbolAddress((void**)&h20, g_hist20);
    cudaGetSymbolAddress((void**)&chk, g_chunk);
    cudaGetSymbolAddress((void**)&sel, g_sel);

    float* trend = scr;                     // sig stride = L0C
    float* ch = scr + (size_t)2 * L0C;      // chain stride = CHAIN
    float* a1 = ch;
    float* d1 = ch + L1P;
    float* a2 = ch + (size_t)2 * L1P;
    float* d2 = a2 + L2P;
    float* a3 = d2 + L2P;
    float* d3 = a3 + L3P;
    float* r2 = d3 + L3P;
    float* r1 = r2 + R2C;

    // zero the 20-bit histograms for this replay (graph-capturable)
    cudaMemsetAsync(h20, 0, (size_t)2 * H20 * sizeof(unsigned int));

    movavg_kernel<<<gridFor((long long)B_ * MA_NCH * N_, 256), 256>>>(x, trend, scr + L0C);

    // forward transforms (both chains per launch)
    dwt4_hist_kernel<<<dim3(gridFor(L1C, 1024), 2), 256>>>(trend, L0C, L0C, a1, d1, CHAIN, L1C, hist);
    select0_kernel<<<2, 256>>>(hist, sel);
    dwt4_kernel<<<dim3(gridFor(L2C, 1024), 2), 256>>>(a1, CHAIN, L1C, a2, d2, CHAIN, L2C);
    dwt4_kernel<<<dim3(gridFor(L3C, 1024), 2), 256>>>(a2, CHAIN, L2C, a3, d3, CHAIN, L3C);

    // single wide median pass (20 bits) + hierarchical select
    const int HB = 592;
    histP20_kernel<<<dim3(HB, 2), 256>>>(d1, CHAIN, L1C, h20, sel);
    reduce20_kernel<<<dim3(1024, 2), 256>>>(h20, chk);
    selectF_kernel<<<2, 256>>>(h20, chk, sel);

    // reconstruction with fused thresholding
    idwt8_kernel<<<dim3(gridFor(R2C, 2048), 2), 256>>>(a3, d3, CHAIN, L3C, r2, CHAIN, sel);
    idwt8_kernel<<<dim3(gridFor(R1C, 2048), 2), 256>>>(r2, d2, CHAIN, L2C, r1, CHAIN, sel);
    fidwt8_kernel<<<dim3(gridFor(L0C, 2048), 2), 256>>>(r1, d1, CHAIN, L1C, trend, L0C, out, sel);

    (void)in_sizes; (void)n_in; (void)out_size;
}

// round 16
// speedup vs baseline: 1.1229x; 1.1229x over previous
#include <cuda_runtime.h>
#include <math.h>

#define B_ 32
#define T_ 720
#define N_ 321

constexpr int L0C = 7395840;          // 32*720*321
constexpr int L1C = 3697927;          // (L0+15)//2
constexpr int L2C = 1848971;
constexpr int L3C = 924493;
constexpr int R2C = 2 * L3C - 14;     // 1848972
constexpr int R1C = 2 * L2C - 14;     // 3697928
constexpr long long KMED = (L1C - 1) / 2;

// padded (16B-aligned) buffer lengths
constexpr int L1P = 3697928;
constexpr int L2P = 1848972;
constexpr int L3P = 924496;

constexpr long long CHAIN = 2LL * L1P + 2LL * L2P + 2LL * L3P + R2C + R1C;
constexpr size_t SCRATCH_SZ = (size_t)2 * L0C + 2 * CHAIN;

constexpr int HB = 592;               // blocks per chain for median scans
constexpr int CAP = 6256;             // compact slots per block (>= 6251 worst case)

// sym8 filters -> FFMA immediates after unroll
__device__ constexpr float LO[16] = {
    -3.3824159510061256e-03f, -5.4213233179114810e-04f,  3.1695087811492980e-02f,
     7.6074873249176050e-03f, -1.4329423835080970e-01f, -6.1273359067658524e-02f,
     4.8135965125837220e-01f,  7.7718575170052350e-01f,  3.6444189483533895e-01f,
    -5.1945838107709040e-02f, -2.7219029917056003e-02f,  4.9137179673607506e-02f,
     3.8087520138906150e-03f, -1.4952258337048230e-02f, -3.0292051472136680e-04f,
     1.8899503327594609e-03f
};
__device__ constexpr float HI[16] = {
    -1.8899503327594609e-03f, -3.0292051472136680e-04f,  1.4952258337048230e-02f,
     3.8087520138906150e-03f, -4.9137179673607506e-02f, -2.7219029917056003e-02f,
     5.1945838107709040e-02f,  3.6444189483533895e-01f, -7.7718575170052350e-01f,
     4.8135965125837220e-01f,  6.1273359067658524e-02f, -1.4329423835080970e-01f,
    -7.6074873249176050e-03f,  3.1695087811492980e-02f,  5.4213233179114810e-04f,
    -3.3824159510061256e-03f
};

struct SelState {
    unsigned int prefix;
    unsigned long long k;
    float lam;
};

__device__ __align__(16) float g_scratch[SCRATCH_SZ];
__device__ unsigned int g_hist[2 * 4096];     // zero-init; re-zeroed by select kernels
__device__ unsigned int g_cnt[2 * HB];        // per-block match counts (overwritten each replay)
__device__ SelState g_sel[2];

// ---------------------------------------------------------------------------
// moving average (K=25, edge-replicated): rolling register ring (R14 WIN)
// ---------------------------------------------------------------------------
#define MA_CH 48
#define MA_NCH (T_ / MA_CH)

__device__ __forceinline__ int clampT(int t) { return min(max(t, 0), T_ - 1); }

__global__ __launch_bounds__(256)
void movavg_kernel(const float* __restrict__ x,
                   float* __restrict__ trend, float* __restrict__ res) {
    int tid = blockIdx.x * blockDim.x + threadIdx.x;
    int total = B_ * MA_NCH * N_;
    if (tid >= total) return;
    int n = tid % N_;
    int r = tid / N_;
    int ch = r % MA_NCH;
    int b = r / MA_NCH;

    const float* xb = x + (size_t)b * T_ * N_ + n;
    float* tb = trend + (size_t)b * T_ * N_ + n;
    float* rb = res + (size_t)b * T_ * N_ + n;

    int t0 = ch * MA_CH;

    float w[26];
    #pragma unroll
    for (int k = 0; k < 25; ++k)
        w[k] = __ldg(xb + (size_t)clampT(t0 - 12 + k) * N_);
    float s = 0.f;
    #pragma unroll
    for (int k = 0; k < 25; ++k) s += w[k];

    #pragma unroll
    for (int st = 0; st < MA_CH; ++st) {
        int t = t0 + st;
        w[(25 + st) % 26] = __ldg(xb + (size_t)clampT(t + 13) * N_);
        float xc = w[(12 + st) % 26];
        float tr = s / 25.0f;
        tb[(size_t)t * N_] = tr;
        rb[(size_t)t * N_] = xc - tr;
        s += w[(25 + st) % 26] - w[st % 26];
    }
}

// ---------------------------------------------------------------------------
// forward DWT, 4 output-pairs per thread (R3)
// ---------------------------------------------------------------------------
__device__ __forceinline__ void dwt_compute4(const float* __restrict__ a, int L,
                                             int tid, float accA[4], float accD[4]) {
    float w[24];
    int s0 = 8 * tid - 16;
    if (s0 >= 0 && s0 + 24 <= L) {
        const float4* p = reinterpret_cast<const float4*>(a + s0);
        #pragma unroll
        for (int q = 0; q < 6; ++q) {
            float4 v = __ldg(p + q);
            w[4*q+0] = v.x; w[4*q+1] = v.y; w[4*q+2] = v.z; w[4*q+3] = v.w;
        }
    } else {
        #pragma unroll
        for (int q = 0; q < 24; ++q) {
            int s = s0 + q;
            if (s < 0) s = -1 - s;
            else if (s >= L) s = 2 * L - 1 - s;
            w[q] = __ldg(a + s);
        }
    }
    #pragma unroll
    for (int c = 0; c < 4; ++c) {
        float sa = 0.f, sd = 0.f;
        #pragma unroll
        for (int t = 0; t < 16; ++t) {
            float v = w[2*c + 17 - t];
            sa = fmaf(v, LO[t], sa);
            sd = fmaf(v, HI[t], sd);
        }
        accA[c] = sa; accD[c] = sd;
    }
}

__global__ __launch_bounds__(256)
void dwt4_kernel(const float* __restrict__ abase, long long astr, int L,
                 float* __restrict__ cabase, float* __restrict__ cdbase,
                 long long cstr, int Lc) {
    int chain = blockIdx.y;
    const float* a = abase + (size_t)chain * astr;
    float* ca = cabase + (size_t)chain * cstr;
    float* cd = cdbase + (size_t)chain * cstr;
    int tid = blockIdx.x * blockDim.x + threadIdx.x;
    int j0 = 4 * tid;
    if (j0 >= Lc) return;
    float accA[4], accD[4];
    dwt_compute4(a, L, tid, accA, accD);
    if (j0 + 4 <= Lc) {
        *reinterpret_cast<float4*>(ca + j0) = make_float4(accA[0], accA[1], accA[2], accA[3]);
        *reinterpret_cast<float4*>(cd + j0) = make_float4(accD[0], accD[1], accD[2], accD[3]);
    } else {
        for (int c = 0; c < 4 && j0 + c < Lc; ++c) { ca[j0+c] = accA[c]; cd[j0+c] = accD[c]; }
    }
}

// level-1 dwt with fused median pass-0 histogram (top 12 bits of |cd|)
__global__ __launch_bounds__(256)
void dwt4_hist_kernel(const float* __restrict__ abase, long long astr, int L,
                      float* __restrict__ cabase, float* __restrict__ cdbase,
                      long long cstr, int Lc, unsigned int* __restrict__ histb) {
    __shared__ unsigned int sh[4096];
    for (int i = threadIdx.x; i < 4096; i += 256) sh[i] = 0u;
    __syncthreads();

    int chain = blockIdx.y;
    int tid = blockIdx.x * blockDim.x + threadIdx.x;
    int j0 = 4 * tid;
    if (j0 < Lc) {
        const float* a = abase + (size_t)chain * astr;
        float* ca = cabase + (size_t)chain * cstr;
        float* cd = cdbase + (size_t)chain * cstr;
        float accA[4], accD[4];
        dwt_compute4(a, L, tid, accA, accD);
        if (j0 + 4 <= Lc) {
            *reinterpret_cast<float4*>(ca + j0) = make_float4(accA[0], accA[1], accA[2], accA[3]);
            *reinterpret_cast<float4*>(cd + j0) = make_float4(accD[0], accD[1], accD[2], accD[3]);
            #pragma unroll
            for (int c = 0; c < 4; ++c)
                atomicAdd(&sh[__float_as_uint(fabsf(accD[c])) >> 20], 1u);
        } else {
            for (int c = 0; c < 4 && j0 + c < Lc; ++c) {
                ca[j0+c] = accA[c]; cd[j0+c] = accD[c];
                atomicAdd(&sh[__float_as_uint(fabsf(accD[c])) >> 20], 1u);
            }
        }
    }
    __syncthreads();
    unsigned int* h = histb + chain * 4096;
    for (int i = threadIdx.x; i < 4096; i += 256) {
        unsigned int c = sh[i];
        if (c) atomicAdd(&h[i], c);
    }
}

// ---------------------------------------------------------------------------
// median pass 1 over d1 (contiguous block ranges): mid-12-bit histogram +
// per-block compaction of matching bit patterns into private regions.
// ---------------------------------------------------------------------------
__global__ __launch_bounds__(256)
void histP1c_kernel(const float* __restrict__ dbase, long long str, int len,
                    unsigned int* __restrict__ histb,
                    const SelState* __restrict__ sel,
                    unsigned int* __restrict__ cmpb, long long cmpstr,
                    unsigned int* __restrict__ cntb) {
    int chain = blockIdx.y;
    const float* d = dbase + (size_t)chain * str;
    unsigned int* hist = histb + chain * 4096;
    unsigned int* cmp = cmpb + (size_t)chain * cmpstr + (size_t)blockIdx.x * CAP;
    unsigned int pfx = sel[chain].prefix;
    __shared__ unsigned int sh[4096];
    __shared__ unsigned int cntS;
    for (int i = threadIdx.x; i < 4096; i += 256) sh[i] = 0u;
    if (threadIdx.x == 0) cntS = 0u;
    __syncthreads();

    int nvec = len >> 2;
    int per = (nvec + gridDim.x - 1) / gridDim.x;
    int i0 = blockIdx.x * per;
    int i1 = min(i0 + per, nvec);
    const float4* dv = reinterpret_cast<const float4*>(d);
    for (int i = i0 + threadIdx.x; i < i1; i += 256) {
        float4 v = __ldg(dv + i);
        float vv[4] = {v.x, v.y, v.z, v.w};
        #pragma unroll
        for (int q = 0; q < 4; ++q) {
            unsigned int u = __float_as_uint(fabsf(vv[q]));
            if ((u >> 20) == pfx) {
                atomicAdd(&sh[(u >> 8) & 0xFFFu], 1u);
                unsigned int idx = atomicAdd(&cntS, 1u);
                cmp[idx] = u;
            }
        }
    }
    if (blockIdx.x == gridDim.x - 1 && threadIdx.x < (len & 3)) {
        unsigned int u = __float_as_uint(fabsf(__ldg(d + (nvec << 2) + threadIdx.x)));
        if ((u >> 20) == pfx) {
            atomicAdd(&sh[(u >> 8) & 0xFFFu], 1u);
            unsigned int idx = atomicAdd(&cntS, 1u);
            cmp[idx] = u;
        }
    }
    __syncthreads();
    for (int i = threadIdx.x; i < 4096; i += 256) {
        unsigned int c = sh[i];
        if (c) atomicAdd(&hist[i], c);
    }
    if (threadIdx.x == 0) cntb[chain * HB + blockIdx.x] = cntS;
}

// ---------------------------------------------------------------------------
// median pass 2: scan only compacted matches (tiny)
// ---------------------------------------------------------------------------
__global__ __launch_bounds__(256)
void histP2c_kernel(const unsigned int* __restrict__ cmpb, long long cmpstr,
                    const unsigned int* __restrict__ cntb,
                    unsigned int* __restrict__ histb,
                    const SelState* __restrict__ sel) {
    int chain = blockIdx.y;
    const unsigned int* cmp = cmpb + (size_t)chain * cmpstr + (size_t)blockIdx.x * CAP;
    unsigned int n = __ldg(cntb + chain * HB + blockIdx.x);
    unsigned int* hist = histb + chain * 4096;
    unsigned int pfx = sel[chain].prefix;   // 24-bit after pass-1 select
    __shared__ unsigned int sh[256];
    if (threadIdx.x < 256) sh[threadIdx.x] = 0u;
    __syncthreads();

    for (unsigned int i = threadIdx.x; i < n; i += 256) {
        unsigned int u = __ldg(cmp + i);
        if ((u >> 8) == pfx) atomicAdd(&sh[u & 0xFFu], 1u);
    }
    __syncthreads();
    if (threadIdx.x < 256) {
        unsigned int c = sh[threadIdx.x];
        if (c) atomicAdd(&hist[threadIdx.x], c);
    }
}

// ---------------------------------------------------------------------------
// radix-select step (standalone; re-zeros hist bins for replay)
// ---------------------------------------------------------------------------
__global__ __launch_bounds__(256)
void select_kernel(unsigned int* __restrict__ histb, SelState* __restrict__ selb,
                   int pass) {
    int chain = blockIdx.x;
    unsigned int* hist = histb + chain * 4096;
    SelState* st = selb + chain;
    __shared__ unsigned int sbins[4096];
    __shared__ unsigned long long ps[256];
    int tid = threadIdx.x;
    unsigned long long s = 0;
    #pragma unroll
    for (int j = 0; j < 16; ++j) {
        unsigned int c = hist[tid * 16 + j];
        sbins[tid * 16 + j] = c;
        s += c;
        hist[tid * 16 + j] = 0u;   // re-zero for next pass / next graph replay
    }
    ps[tid] = s;
    __syncthreads();
    if (tid == 0) {
        long long k = (pass == 0) ? (long long)KMED : (long long)st->k;
        long long cum = 0;
        int chunk = 0;
        for (; chunk < 255; ++chunk) {
            if (cum + (long long)ps[chunk] > k) break;
            cum += (long long)ps[chunk];
        }
        int b = chunk * 16;
        for (;; ++b) {
            unsigned int c = sbins[b];
            if (cum + (long long)c > k) break;
            cum += c;
        }
        st->k = (unsigned long long)(k - cum);
        if (pass == 0) {
            st->prefix = (unsigned int)b;
        } else if (pass == 1) {
            st->prefix = (st->prefix << 12) | (unsigned int)b;
        } else {
            unsigned int u = (st->prefix << 8) | (unsigned int)b;
            float med = __uint_as_float(u);
            st->lam = (med / 0.6745f) * (float)sqrt(2.0 * log((double)L0C));
        }
    }
}

// ---------------------------------------------------------------------------
// inverse DWT with fused thresholding, 8 outputs/thread (R3)
// ---------------------------------------------------------------------------
__device__ __forceinline__ float thrf(float d, float lam, float alam) {
    float ad = fabsf(d);
    return (ad >= lam) ? copysignf(ad - alam, d) : 0.0f;
}

__device__ __forceinline__ void idwt_compute8(const float* __restrict__ ca,
                                              const float* __restrict__ cd,
                                              int Lc, int t, float lam, float alam,
                                              float o[8]) {
    int i0 = 4 * t;
    float A[12], D[12];
    if (i0 + 12 <= Lc) {
        const float4* pa = reinterpret_cast<const float4*>(ca + i0);
        const float4* pd = reinterpret_cast<const float4*>(cd + i0);
        #pragma unroll
        for (int q = 0; q < 3; ++q) {
            float4 va = __ldg(pa + q);
            A[4*q+0] = va.x; A[4*q+1] = va.y; A[4*q+2] = va.z; A[4*q+3] = va.w;
            float4 vd = __ldg(pd + q);
            D[4*q+0] = thrf(vd.x, lam, alam); D[4*q+1] = thrf(vd.y, lam, alam);
            D[4*q+2] = thrf(vd.z, lam, alam); D[4*q+3] = thrf(vd.w, lam, alam);
        }
    } else {
        #pragma unroll
        for (int q = 0; q < 12; ++q) {
            int i = i0 + q;
            bool ok = i < Lc;
            A[q] = ok ? __ldg(ca + i) : 0.f;
            D[q] = ok ? thrf(__ldg(cd + i), lam, alam) : 0.f;
        }
    }
    #pragma unroll
    for (int c = 0; c < 8; ++c) {
        int base = c >> 1;
        int tb = (c & 1) ? 0 : 1;
        float v = 0.f;
        #pragma unroll
        for (int r = 0; r < 8; ++r) {
            v = fmaf(A[base + r], LO[2*r + tb], v);
            v = fmaf(D[base + r], HI[2*r + tb], v);
        }
        o[c] = v;
    }
}

__global__ __launch_bounds__(256)
void idwt8_kernel(const float* __restrict__ cabase, const float* __restrict__ cdbase,
                  long long str, int Lc, float* __restrict__ outbase, long long ostr,
                  const SelState* __restrict__ sel) {
    int chain = blockIdx.y;
    const float* ca = cabase + (size_t)chain * str;
    const float* cd = cdbase + (size_t)chain * str;
    float* out = outbase + (size_t)chain * ostr;
    int t = blockIdx.x * blockDim.x + threadIdx.x;
    int Lout = 2 * Lc - 14;
    int k0 = 8 * t;
    if (k0 >= Lout) return;
    float lam = sel[chain].lam, alam = 0.85f * lam;
    float o[8];
    idwt_compute8(ca, cd, Lc, t, lam, alam, o);
    if (k0 + 8 <= Lout) {
        *reinterpret_cast<float4*>(out + k0)     = make_float4(o[0], o[1], o[2], o[3]);
        *reinterpret_cast<float4*>(out + k0 + 4) = make_float4(o[4], o[5], o[6], o[7]);
    } else {
        for (int c = 0; c < 8 && k0 + c < Lout; ++c) out[k0 + c] = o[c];
    }
}

// final level: fuse the four output writes
__global__ __launch_bounds__(256)
void fidwt8_kernel(const float* __restrict__ cabase, const float* __restrict__ cdbase,
                   long long str, int Lc, const float* __restrict__ sigbase,
                   long long sstr, float* __restrict__ out,
                   const SelState* __restrict__ sel) {
    int chain = blockIdx.y;
    const float* ca = cabase + (size_t)chain * str;
    const float* cd = cdbase + (size_t)chain * str;
    const float* sig = sigbase + (size_t)chain * sstr;
    float* out_diff = out + (size_t)(2 * chain) * L0C;
    float* out_nn   = out + (size_t)(2 * chain + 1) * L0C;
    int t = blockIdx.x * blockDim.x + threadIdx.x;
    int Lout = 2 * Lc - 14;   // == L0C (mult of 8)
    int k0 = 8 * t;
    if (k0 >= Lout) return;
    float lam = sel[chain].lam, alam = 0.85f * lam;
    float o[8];
    idwt_compute8(ca, cd, Lc, t, lam, alam, o);
    float4 s0 = __ldg(reinterpret_cast<const float4*>(sig + k0));
    float4 s1 = __ldg(reinterpret_cast<const float4*>(sig + k0 + 4));
    *reinterpret_cast<float4*>(out_nn + k0)     = make_float4(o[0], o[1], o[2], o[3]);
    *reinterpret_cast<float4*>(out_nn + k0 + 4) = make_float4(o[4], o[5], o[6], o[7]);
    *reinterpret_cast<float4*>(out_diff + k0) =
        make_float4(s0.x - o[0], s0.y - o[1], s0.z - o[2], s0.w - o[3]);
    *reinterpret_cast<float4*>(out_diff + k0 + 4) =
        make_float4(s1.x - o[4], s1.y - o[5], s1.z - o[6], s1.w - o[7]);
}

// ---------------------------------------------------------------------------
static inline int gridFor(long long n, int per) { return (int)((n + per - 1) / per); }

extern "C" void kernel_launch(void* const* d_in, const int* in_sizes, int n_in,
                              void* d_out, int out_size) {
    const float* x = (const float*)d_in[0];
    float* out = (float*)d_out;

    float* scr = nullptr;
    unsigned int* hist = nullptr;
    unsigned int* cnt = nullptr;
    SelState* sel = nullptr;
    cudaGetSymbolAddress((void**)&scr, g_scratch);
    cudaGetSymbolAddress((void**)&hist, g_hist);
    cudaGetSymbolAddress((void**)&cnt, g_cnt);
    cudaGetSymbolAddress((void**)&sel, g_sel);

    float* trend = scr;                     // sig stride = L0C
    float* ch = scr + (size_t)2 * L0C;      // chain stride = CHAIN
    float* a1 = ch;
    float* d1 = ch + L1P;
    float* a2 = ch + (size_t)2 * L1P;
    float* d2 = a2 + L2P;
    float* a3 = d2 + L2P;
    float* d3 = a3 + L3P;
    float* r2 = d3 + L3P;
    float* r1 = r2 + R2C;
    // compact regions live in r2+r1 (written only later by the idwt stage)
    unsigned int* cmp = reinterpret_cast<unsigned int*>(r2);

    movavg_kernel<<<gridFor((long long)B_ * MA_NCH * N_, 256), 256>>>(x, trend, scr + L0C);

    // forward transforms (both chains per launch)
    dwt4_hist_kernel<<<dim3(gridFor(L1C, 1024), 2), 256>>>(trend, L0C, L0C, a1, d1, CHAIN, L1C, hist);
    select_kernel<<<2, 256>>>(hist, sel, 0);
    dwt4_kernel<<<dim3(gridFor(L2C, 1024), 2), 256>>>(a1, CHAIN, L1C, a2, d2, CHAIN, L2C);
    dwt4_kernel<<<dim3(gridFor(L3C, 1024), 2), 256>>>(a2, CHAIN, L2C, a3, d3, CHAIN, L3C);

    // median: full scan + compaction, then tiny pass 2 over compacted matches
    histP1c_kernel<<<dim3(HB, 2), 256>>>(d1, CHAIN, L1C, hist, sel, cmp, CHAIN, cnt);
    select_kernel<<<2, 256>>>(hist, sel, 1);
    histP2c_kernel<<<dim3(HB, 2), 256>>>(cmp, CHAIN, cnt, hist, sel);
    select_kernel<<<2, 256>>>(hist, sel, 2);

    // reconstruction with fused thresholding
    idwt8_kernel<<<dim3(gridFor(R2C, 2048), 2), 256>>>(a3, d3, CHAIN, L3C, r2, CHAIN, sel);
    idwt8_kernel<<<dim3(gridFor(R1C, 2048), 2), 256>>>(r2, d2, CHAIN, L2C, r1, CHAIN, sel);
    fidwt8_kernel<<<dim3(gridFor(L0C, 2048), 2), 256>>>(r1, d1, CHAIN, L1C, trend, L0C, out, sel);

    (void)in_sizes; (void)n_in; (void)out_size;
}